// round 5
// baseline (speedup 1.0000x reference)
#include <cuda_runtime.h>
#include <math.h>

#define N_NODES 40000
#define FEAT    128
#define HID     128
#define EMB     64
#define N_EDGES 640000

// Scratch: device globals (allocation-free per harness rules).
__device__ __align__(16) float g_agg[N_NODES * FEAT];
__device__ float g_cnt[N_NODES];
__device__ float g_rcnt[N_NODES];
__device__ __align__(16) float g_h[N_NODES * HID];

// ---------------------------------------------------------------------------
// zero g_agg (+ g_cnt)
__global__ void k_zero(int do_cnt) {
    int i = blockIdx.x * blockDim.x + threadIdx.x;
    const int n4 = N_NODES * FEAT / 4;
    if (i < n4) ((float4*)g_agg)[i] = make_float4(0.f, 0.f, 0.f, 0.f);
    if (do_cnt && i < N_NODES) g_cnt[i] = 0.f;
}

// ---------------------------------------------------------------------------
// scatter-add: one warp per edge, 32 lanes x 4 floats = 128 floats.
// Indices are int32 (JAX default x64-disabled downcasts jnp.int64 -> int32).
__global__ void k_scatter(const int* __restrict__ src,
                          const int* __restrict__ dst,
                          const float* __restrict__ feat,
                          int use_gh, int do_cnt) {
    int w    = (blockIdx.x * blockDim.x + threadIdx.x) >> 5;
    int lane = threadIdx.x & 31;
    if (w >= N_EDGES) return;
    int s = src[w];
    int d = dst[w];
    if ((unsigned)s >= N_NODES || (unsigned)d >= N_NODES) return;  // insurance
    const float* f = use_gh ? g_h : feat;
    float4 v = ((const float4*)(f + (size_t)s * 128))[lane];
    float* p = g_agg + (size_t)d * 128 + lane * 4;
    atomicAdd(p + 0, v.x);
    atomicAdd(p + 1, v.y);
    atomicAdd(p + 2, v.z);
    atomicAdd(p + 3, v.w);
    if (do_cnt && lane == 0) atomicAdd(g_cnt + d, 1.0f);
}

// ---------------------------------------------------------------------------
__global__ void k_rcnt() {
    int i = blockIdx.x * blockDim.x + threadIdx.x;
    if (i < N_NODES) g_rcnt[i] = 1.0f / fmaxf(g_cnt[i], 1.0f);
}

// ---------------------------------------------------------------------------
// out[n][j] = (g_agg[n]*g_rcnt[n]) . Wl[j] + bias[j] + xin[n] . Wr[j], opt ELU.
// Static smem only (16KB node rows); weights streamed via __ldg (L1-resident).
// 256 threads; SLOTS = 256/DOUT parallel node-slots; NB nodes per slot.
template<int DOUT, int NB>
__global__ __launch_bounds__(256)
void k_gemm(const float* __restrict__ xin_p,
            const float* __restrict__ Wl, const float* __restrict__ Wr,
            const float* __restrict__ bias, float* out_p,
            int do_elu, int use_gh_in, int use_gh_out) {
    constexpr int SLOTS = 256 / DOUT;
    constexpr int NBT   = NB * SLOTS;          // nodes per tile (= 16)
    static_assert(NBT == 16, "tile size");

    const float* xin = use_gh_in  ? g_h : xin_p;
    float*       out = use_gh_out ? g_h : out_p;

    __shared__ float rows_x[16 * 128];
    __shared__ float rows_a[16 * 128];

    const int tid  = threadIdx.x;
    const int j    = tid % DOUT;
    const int slot = tid / DOUT;

    const float4* wl4 = (const float4*)(Wl + j * 128);
    const float4* wr4 = (const float4*)(Wr + j * 128);
    const float   bj  = __ldg(bias + j);

    const int numTiles = (N_NODES + NBT - 1) / NBT;
    for (int tile = blockIdx.x; tile < numTiles; tile += gridDim.x) {
        int base = tile * NBT;

        for (int idx = tid; idx < NBT * 128; idx += 256) {
            int ln = idx >> 7, k = idx & 127;
            int node = base + ln;
            float xv = 0.f, av = 0.f;
            if (node < N_NODES) {
                xv = xin[(size_t)node * 128 + k];
                av = g_agg[(size_t)node * 128 + k] * g_rcnt[node];
            }
            rows_x[ln * 128 + k] = xv;
            rows_a[ln * 128 + k] = av;
        }
        __syncthreads();

        float acc[NB];
        #pragma unroll
        for (int i = 0; i < NB; i++) acc[i] = bj;

        #pragma unroll
        for (int k4 = 0; k4 < 32; k4++) {
            float4 wl = __ldg(wl4 + k4);
            float4 wr = __ldg(wr4 + k4);
            #pragma unroll
            for (int i = 0; i < NB; i++) {
                int ln = slot * NB + i;
                float4 av = ((const float4*)(rows_a + ln * 128))[k4];
                float4 xv = ((const float4*)(rows_x + ln * 128))[k4];
                acc[i] += av.x * wl.x + av.y * wl.y + av.z * wl.z + av.w * wl.w
                        + xv.x * wr.x + xv.y * wr.y + xv.z * wr.z + xv.w * wr.w;
            }
        }

        #pragma unroll
        for (int i = 0; i < NB; i++) {
            int node = base + slot * NB + i;
            if (node < N_NODES) {
                float v = acc[i];
                if (do_elu) v = (v > 0.f) ? v : expm1f(v);
                out[(size_t)node * DOUT + j] = v;
            }
        }
        __syncthreads();
    }
}

// ---------------------------------------------------------------------------
// log_softmax over 64 columns: one warp per node, 2 elems per lane
__global__ void k_lsm(float* __restrict__ out) {
    int n    = (blockIdx.x * blockDim.x + threadIdx.x) >> 5;
    int lane = threadIdx.x & 31;
    if (n >= N_NODES) return;
    float v0 = out[(size_t)n * 64 + lane];
    float v1 = out[(size_t)n * 64 + 32 + lane];
    float m = fmaxf(v0, v1);
    #pragma unroll
    for (int o = 16; o; o >>= 1) m = fmaxf(m, __shfl_xor_sync(0xFFFFFFFFu, m, o));
    float s = expf(v0 - m) + expf(v1 - m);
    #pragma unroll
    for (int o = 16; o; o >>= 1) s += __shfl_xor_sync(0xFFFFFFFFu, s, o);
    float l = m + logf(s);
    out[(size_t)n * 64 + lane]      = v0 - l;
    out[(size_t)n * 64 + 32 + lane] = v1 - l;
}

// ---------------------------------------------------------------------------
extern "C" void kernel_launch(void* const* d_in, const int* in_sizes, int n_in,
                              void* d_out, int out_size) {
    const float* x   = (const float*)d_in[0];
    const int*   src = (const int*)d_in[1];            // edge_index row 0 (int32)
    const int*   dst = src + N_EDGES;                  // edge_index row 1 (int32)
    const float* W1l = (const float*)d_in[2];
    const float* b1  = (const float*)d_in[3];
    const float* W1r = (const float*)d_in[4];
    const float* W2l = (const float*)d_in[5];
    const float* b2  = (const float*)d_in[6];
    const float* W2r = (const float*)d_in[7];
    float* out = (float*)d_out;

    const int n4 = N_NODES * FEAT / 4;
    const int zgrid = (n4 + 255) / 256;
    const int sgrid = (N_EDGES * 32 + 255) / 256;   // one warp per edge

    // ---- layer 1 ----
    k_zero<<<zgrid, 256>>>(1);
    k_scatter<<<sgrid, 256>>>(src, dst, x, 0, 1);
    k_rcnt<<<(N_NODES + 255) / 256, 256>>>();
    k_gemm<128, 8><<<296, 256>>>(x, W1l, W1r, b1, nullptr, 1, 0, 1);

    // ---- layer 2 ----
    k_zero<<<zgrid, 256>>>(0);
    k_scatter<<<sgrid, 256>>>(src, dst, nullptr, 1, 0);
    k_gemm<64, 4><<<296, 256>>>(nullptr, W2l, W2r, b2, out, 0, 1, 0);

    // ---- log_softmax (in place on d_out) ----
    k_lsm<<<(N_NODES * 32 + 255) / 256, 256>>>(out);
}

// round 6
// speedup vs baseline: 2.5435x; 2.5435x over previous
#include <cuda_runtime.h>
#include <math.h>

#define N_NODES 40000
#define FEAT    128
#define HID     128
#define EMB     64
#define N_EDGES 640000

// Scratch: device globals (allocation-free per harness rules).
__device__ __align__(16) float g_agg[N_NODES * FEAT];
__device__ __align__(16) float g_h[N_NODES * HID];
__device__ int g_deg[N_NODES];
__device__ int g_rowptr[N_NODES + 1];
__device__ int g_woff[N_NODES];
__device__ int g_esrc[N_EDGES];

// ---------------------------------------------------------------------------
__global__ void k_dzero() {
    int i = blockIdx.x * blockDim.x + threadIdx.x;
    if (i < N_NODES) g_deg[i] = 0;
}

__global__ void k_hist(const int* __restrict__ dst) {
    int e = blockIdx.x * blockDim.x + threadIdx.x;
    if (e >= N_EDGES) return;
    int d = dst[e];
    if ((unsigned)d < N_NODES) atomicAdd(&g_deg[d], 1);
}

// single-block exclusive prefix scan of g_deg -> g_rowptr, g_woff
__global__ __launch_bounds__(1024) void k_scan() {
    __shared__ int ssum[1024];
    const int t = threadIdx.x;
    const int CH = 40;                       // 1024*40 >= 40000
    int base = t * CH;
    int tsum = 0;
    for (int c = 0; c < CH; c++) {
        int idx = base + c;
        if (idx < N_NODES) tsum += g_deg[idx];
    }
    ssum[t] = tsum;
    __syncthreads();
    for (int off = 1; off < 1024; off <<= 1) {
        int v = (t >= off) ? ssum[t - off] : 0;
        __syncthreads();
        ssum[t] += v;
        __syncthreads();
    }
    int running = ssum[t] - tsum;            // exclusive prefix
    for (int c = 0; c < CH; c++) {
        int idx = base + c;
        if (idx < N_NODES) {
            g_rowptr[idx] = running;
            g_woff[idx]   = running;
            running += g_deg[idx];
        }
    }
    if (t == 1023) g_rowptr[N_NODES] = running;
}

__global__ void k_permute(const int* __restrict__ src, const int* __restrict__ dst) {
    int e = blockIdx.x * blockDim.x + threadIdx.x;
    if (e >= N_EDGES) return;
    int d = dst[e], s = src[e];
    if ((unsigned)d >= N_NODES || (unsigned)s >= N_NODES) return;
    int pos = atomicAdd(&g_woff[d], 1);
    g_esrc[pos] = s;
}

// ---------------------------------------------------------------------------
// gather-aggregate (mean): one warp per dst node, 32 lanes x float4 = 128 floats
__global__ void k_agg(const float4* __restrict__ feat_p, int use_gh) {
    int w    = (blockIdx.x * blockDim.x + threadIdx.x) >> 5;
    int lane = threadIdx.x & 31;
    if (w >= N_NODES) return;
    const float4* feat = use_gh ? (const float4*)g_h : feat_p;
    int beg = g_rowptr[w];
    int end = g_rowptr[w + 1];
    float4 acc = make_float4(0.f, 0.f, 0.f, 0.f);
    int i = beg;
    for (; i + 4 <= end; i += 4) {                  // 4-wide MLP gathers
        int s0 = g_esrc[i + 0], s1 = g_esrc[i + 1];
        int s2 = g_esrc[i + 2], s3 = g_esrc[i + 3];
        float4 v0 = feat[s0 * 32 + lane];
        float4 v1 = feat[s1 * 32 + lane];
        float4 v2 = feat[s2 * 32 + lane];
        float4 v3 = feat[s3 * 32 + lane];
        acc.x += v0.x + v1.x + v2.x + v3.x;
        acc.y += v0.y + v1.y + v2.y + v3.y;
        acc.z += v0.z + v1.z + v2.z + v3.z;
        acc.w += v0.w + v1.w + v2.w + v3.w;
    }
    for (; i < end; i++) {
        float4 v = feat[g_esrc[i] * 32 + lane];
        acc.x += v.x; acc.y += v.y; acc.z += v.z; acc.w += v.w;
    }
    float r = 1.0f / (float)max(end - beg, 1);
    acc.x *= r; acc.y *= r; acc.z *= r; acc.w *= r;
    ((float4*)g_agg)[w * 32 + lane] = acc;
}

// ---------------------------------------------------------------------------
// out[n][j] = g_agg[n].Wl[j] + b[j] + xin[n].Wr[j]   (agg already mean-scaled)
// Transposed weights in smem (conflict-free LDS.128), rows as float2 broadcast.
// 256 threads; thread computes 4 rows x 4 cols.
template<int DOUT, int NTILE>
__global__ __launch_bounds__(256)
void k_gemm(const float* __restrict__ xin_p,
            const float* __restrict__ Wl, const float* __restrict__ Wr,
            const float* __restrict__ bias, float* __restrict__ out_p,
            int do_elu, int use_gh_in, int use_gh_out) {
    constexpr int CT = DOUT / 4;            // col-thread count (32 / 16)
    constexpr int RT = 256 / CT;            // row-thread count (8 / 16)
    constexpr int NR = NTILE / RT;          // rows per thread (4)
    constexpr int WP = DOUT + 4;            // smem weight pitch (floats)
    static_assert(NR == 4, "rows per thread");

    const float* xin = use_gh_in  ? g_h : xin_p;
    float*       out = use_gh_out ? g_h : out_p;

    extern __shared__ float sm[];
    float*  wt_l = sm;                       // [128][WP] transposed
    float*  wt_r = wt_l + 128 * WP;          // [128][WP]
    float2* rows = (float2*)(wt_r + 128 * WP);  // [NTILE][128] {agg, x}

    const int tid = threadIdx.x;
    const int cx  = tid % CT;               // col group (4 cols)
    const int rx  = tid / CT;               // row group (4 rows)

    // load weights transposed: wt[k][j] = W[j][k]
    for (int idx = tid; idx < DOUT * 128; idx += 256) {
        int j = idx >> 7, k = idx & 127;
        wt_l[k * WP + j] = Wl[idx];
        wt_r[k * WP + j] = Wr[idx];
    }
    float4 bj = ((const float4*)bias)[cx];
    __syncthreads();

    const int numTiles = (N_NODES + NTILE - 1) / NTILE;
    for (int tile = blockIdx.x; tile < numTiles; tile += gridDim.x) {
        int base = tile * NTILE;

        for (int idx = tid; idx < NTILE * 128; idx += 256) {
            int ln = idx >> 7, k = idx & 127;
            int node = base + ln;
            float av = 0.f, xv = 0.f;
            if (node < N_NODES) {
                av = g_agg[(size_t)node * 128 + k];
                xv = xin[(size_t)node * 128 + k];
            }
            rows[ln * 128 + k] = make_float2(av, xv);
        }
        __syncthreads();

        float acc[4][4];
        #pragma unroll
        for (int i = 0; i < 4; i++)
            #pragma unroll
            for (int c = 0; c < 4; c++) acc[i][c] = 0.f;

        const float2* rbase = rows + (rx * NR) * 128;
        #pragma unroll 4
        for (int k = 0; k < 128; k++) {
            float4 wl = *(const float4*)(wt_l + k * WP + cx * 4);
            float4 wr = *(const float4*)(wt_r + k * WP + cx * 4);
            #pragma unroll
            for (int i = 0; i < 4; i++) {
                float2 ax = rbase[i * 128 + k];
                acc[i][0] += ax.x * wl.x + ax.y * wr.x;
                acc[i][1] += ax.x * wl.y + ax.y * wr.y;
                acc[i][2] += ax.x * wl.z + ax.y * wr.z;
                acc[i][3] += ax.x * wl.w + ax.y * wr.w;
            }
        }

        #pragma unroll
        for (int i = 0; i < 4; i++) {
            int node = base + rx * NR + i;
            if (node < N_NODES) {
                float4 o;
                o.x = acc[i][0] + bj.x;
                o.y = acc[i][1] + bj.y;
                o.z = acc[i][2] + bj.z;
                o.w = acc[i][3] + bj.w;
                if (do_elu) {
                    o.x = (o.x > 0.f) ? o.x : expm1f(o.x);
                    o.y = (o.y > 0.f) ? o.y : expm1f(o.y);
                    o.z = (o.z > 0.f) ? o.z : expm1f(o.z);
                    o.w = (o.w > 0.f) ? o.w : expm1f(o.w);
                }
                ((float4*)(out + (size_t)node * DOUT))[cx] = o;
            }
        }
        __syncthreads();
    }
}

// ---------------------------------------------------------------------------
// log_softmax over 64 columns: one warp per node, 2 elems per lane
__global__ void k_lsm(float* __restrict__ out) {
    int n    = (blockIdx.x * blockDim.x + threadIdx.x) >> 5;
    int lane = threadIdx.x & 31;
    if (n >= N_NODES) return;
    float v0 = out[(size_t)n * 64 + lane];
    float v1 = out[(size_t)n * 64 + 32 + lane];
    float m = fmaxf(v0, v1);
    #pragma unroll
    for (int o = 16; o; o >>= 1) m = fmaxf(m, __shfl_xor_sync(0xFFFFFFFFu, m, o));
    float s = expf(v0 - m) + expf(v1 - m);
    #pragma unroll
    for (int o = 16; o; o >>= 1) s += __shfl_xor_sync(0xFFFFFFFFu, s, o);
    float l = m + logf(s);
    out[(size_t)n * 64 + lane]      = v0 - l;
    out[(size_t)n * 64 + 32 + lane] = v1 - l;
}

// ---------------------------------------------------------------------------
extern "C" void kernel_launch(void* const* d_in, const int* in_sizes, int n_in,
                              void* d_out, int out_size) {
    const float* x   = (const float*)d_in[0];
    const int*   src = (const int*)d_in[1];            // edge_index row 0 (int32)
    const int*   dst = src + N_EDGES;                  // edge_index row 1 (int32)
    const float* W1l = (const float*)d_in[2];
    const float* b1  = (const float*)d_in[3];
    const float* W1r = (const float*)d_in[4];
    const float* W2l = (const float*)d_in[5];
    const float* b2  = (const float*)d_in[6];
    const float* W2r = (const float*)d_in[7];
    float* out = (float*)d_out;

    const int smem1 = (2 * 128 * 132) * 4 + 32 * 128 * 8;   // 167936 B
    const int smem2 = (2 * 128 * 68)  * 4 + 64 * 128 * 8;   // 135168 B
    cudaFuncSetAttribute(k_gemm<128, 32>, cudaFuncAttributeMaxDynamicSharedMemorySize, smem1);
    cudaFuncSetAttribute(k_gemm<64, 64>,  cudaFuncAttributeMaxDynamicSharedMemorySize, smem2);

    const int egrid = (N_EDGES + 255) / 256;
    const int agrid = (N_NODES * 32 + 255) / 256;      // one warp per node

    // ---- CSR build (shared by both layers) ----
    k_dzero<<<(N_NODES + 255) / 256, 256>>>();
    k_hist<<<egrid, 256>>>(dst);
    k_scan<<<1, 1024>>>();
    k_permute<<<egrid, 256>>>(src, dst);

    // ---- layer 1 ----
    k_agg<<<agrid, 256>>>((const float4*)x, 0);
    k_gemm<128, 32><<<148, 256, smem1>>>(x, W1l, W1r, b1, nullptr, 1, 0, 1);

    // ---- layer 2 ----
    k_agg<<<agrid, 256>>>(nullptr, 1);
    k_gemm<64, 64><<<148, 256, smem2>>>(nullptr, W2l, W2r, b2, out, 0, 1, 0);

    // ---- log_softmax (in place on d_out) ----
    k_lsm<<<agrid, 256>>>(out);
}